// round 11
// baseline (speedup 1.0000x reference)
#include <cuda_runtime.h>
#include <cstdint>
#include <cstddef>

// LowRankINRLayer: out = relu( (x @ v^T) @ W^T )
//   x [16,8192,512] f32, v [16,32,512] f32, W [512,32] f32 -> out f32
//
// Round 11: round-10 two-phase streaming design with the three indexing bugs
// fixed (prep grid 64->1024; xv store/load mappings row=idx>>3, u=idx&7).
//   A: xv = x @ v^T   (read-streaming; R7 mainloop, 3 CTAs/SM, tiny store)
//   B: out = relu(xv @ W^T) (write-streaming; R7 staged-STG.128 epilogue)

namespace {

constexpr int kB  = 16;
constexpr int kN  = 8192;
constexpr int kDI = 512;
constexpr int kDO = 512;
constexpr int kR  = 32;

constexpr int TM      = 128;          // rows per tile
constexpr int KC      = 32;           // K per pipeline chunk
constexpr int NCH     = kDI / KC;     // 16
constexpr int STAGES  = 3;
constexpr int THREADS = 256;          // 8 warps

constexpr int XW = KC + 4;                          // 36 words row stride
constexpr int XBUF = TM * XW;                       // 4608 words / stage
constexpr int VBUF = kR * XW;                       // 1152 words / stage
constexpr int V_OFF = STAGES * XBUF;                // 13824
constexpr int SMEM_A_WORDS = V_OFF + STAGES * VBUF; // 17280
constexpr int SMEM_A = SMEM_A_WORDS * 4;            // 69120 B -> 3 CTAs/SM

// kernel B smem: xv tile (128 x 36 words) + 8 warp staging buffers (16x64)
constexpr int STG_OFF = TM * XW;                    // word 4608
constexpr int STG_PER_WARP = 16 * 64;               // 1024 words
constexpr int SMEM_B = (STG_OFF + 8 * STG_PER_WARP) * 4;   // 51200 B

// scratch: xv [b][n][r] f32 (16 MB) ; v as tf32(RNA) blocked [b][ck][n][kk]
__device__ float    g_xv[kB * kN * kR];
__device__ unsigned g_v[kB * kR * kDI];

__device__ __forceinline__ unsigned f2tf(float f) {
    unsigned u;
    asm("cvt.rna.tf32.f32 %0, %1;" : "=r"(u) : "f"(f));
    return u;
}

__device__ __forceinline__ void mma_tf32(float& d0, float& d1, float& d2, float& d3,
                                         unsigned a0, unsigned a1, unsigned a2, unsigned a3,
                                         unsigned b0, unsigned b1) {
    asm volatile(
        "mma.sync.aligned.m16n8k8.row.col.f32.tf32.tf32.f32 "
        "{%0,%1,%2,%3}, {%4,%5,%6,%7}, {%8,%9}, {%0,%1,%2,%3};"
        : "+f"(d0), "+f"(d1), "+f"(d2), "+f"(d3)
        : "r"(a0), "r"(a1), "r"(a2), "r"(a3), "r"(b0), "r"(b1));
}

__device__ __forceinline__ void cp16(unsigned dst_smem, const void* src) {
    asm volatile("cp.async.cg.shared.global [%0], [%1], 16;"
                 :: "r"(dst_smem), "l"(src) : "memory");
}

// ---- prep: v -> tf32 RNA blocked [b][ck][n][kk] (262144 elements) ----
__global__ void prep_kernel(const float* __restrict__ v) {
    int idx = blockIdx.x * 256 + threadIdx.x;   // grid 1024 x 256 = 262144
    int b = idx >> 14, rem = idx & 16383;
    int n = rem >> 9, k = rem & 511;
    int ck = k >> 5, kk = k & 31;
    g_v[(b << 14) + (ck << 10) + (n << 5) + kk] = f2tf(v[idx]);
}

// ==== Kernel A: xv = x @ v^T  (per tile: 128 rows x 32 cols) ====
__global__ void __launch_bounds__(THREADS, 3)
gemm1_kernel(const float* __restrict__ x)
{
    extern __shared__ unsigned smu[];
    const unsigned sbase = (unsigned)__cvta_generic_to_shared(smu);

    const int tid  = threadIdx.x;
    const int lane = tid & 31;
    const int warp = tid >> 5;
    const int g    = lane >> 2;
    const int t4   = lane & 3;
    const int mw   = warp * 16;

    const int b  = blockIdx.x >> 6;
    const int m0 = (blockIdx.x & 63) * TM;

    const float*    xg  = x + ((size_t)b * kN + m0) * kDI;
    const unsigned* gvb = g_v + (size_t)b * (kR * kDI);

    const int vr = tid >> 3, vu = tid & 7;

    auto issue = [&](int c) {
        const int s = c % STAGES;
        const unsigned xd = sbase + (unsigned)(s * XBUF) * 4u;
        #pragma unroll
        for (int i = 0; i < 4; i++) {
            const int q = tid + 256 * i;     // 1024 x 16B units
            const int r = q >> 3, u = q & 7;
            cp16(xd + (unsigned)(r * XW + u * 4) * 4u,
                 xg + (size_t)r * kDI + c * KC + u * 4);
        }
        const unsigned vd = sbase + (unsigned)(V_OFF + s * VBUF) * 4u;
        cp16(vd + (unsigned)(vr * XW + vu * 4) * 4u,
             gvb + c * (kR * KC) + vr * KC + vu * 4);
        asm volatile("cp.async.commit_group;" ::: "memory");
    };

    issue(0); issue(1);

    float acc[4][4] = {};

    for (int c = 0; c < NCH; ++c) {
        if (c < NCH - 1) asm volatile("cp.async.wait_group 1;" ::: "memory");
        else             asm volatile("cp.async.wait_group 0;" ::: "memory");
        __syncthreads();

        if (c + 2 < NCH) issue(c + 2);

        const float*    xb = (const float*)(smu + (c % STAGES) * XBUF);
        const unsigned* vb = smu + V_OFF + (c % STAGES) * VBUF;

        #pragma unroll
        for (int ks = 0; ks < 4; ks++) {
            const int k0 = ks * 8;
            unsigned a0 = f2tf(xb[(mw + g)     * XW + k0 + t4]);
            unsigned a1 = f2tf(xb[(mw + g + 8) * XW + k0 + t4]);
            unsigned a2 = f2tf(xb[(mw + g)     * XW + k0 + t4 + 4]);
            unsigned a3 = f2tf(xb[(mw + g + 8) * XW + k0 + t4 + 4]);
            #pragma unroll
            for (int nb = 0; nb < 4; nb++) {
                unsigned b0 = vb[(nb * 8 + g) * XW + k0 + t4];
                unsigned b1 = vb[(nb * 8 + g) * XW + k0 + t4 + 4];
                mma_tf32(acc[nb][0], acc[nb][1], acc[nb][2], acc[nb][3],
                         a0, a1, a2, a3, b0, b1);
            }
        }
    }

    // acc -> smem (stage-0 region, stride 36) -> coalesced STG.128 to g_xv
    __syncthreads();
    float* c1 = (float*)smu;
    #pragma unroll
    for (int nb = 0; nb < 4; nb++) {
        *reinterpret_cast<float2*>(&c1[(mw + g)     * XW + nb * 8 + 2 * t4]) =
            make_float2(acc[nb][0], acc[nb][1]);
        *reinterpret_cast<float2*>(&c1[(mw + g + 8) * XW + nb * 8 + 2 * t4]) =
            make_float2(acc[nb][2], acc[nb][3]);
    }
    __syncthreads();

    // 128 rows x 32 floats = 1024 float4s: row = idx>>3, u = idx&7
    float* xvg = g_xv + ((size_t)b * kN + m0) * kR;
    #pragma unroll
    for (int i = 0; i < 4; i++) {
        const int idx = tid + 256 * i;
        const int row = idx >> 3, u = idx & 7;
        float4 val = *reinterpret_cast<float4*>(&c1[row * XW + 4 * u]);
        *reinterpret_cast<float4*>(&xvg[(size_t)row * kR + 4 * u]) = val;
    }
}

// ==== Kernel B: out = relu(xv @ W^T)  (per tile: 128 rows x 512 o-cols) ====
__global__ void __launch_bounds__(THREADS, 2)
gemm2_kernel(const float* __restrict__ W, float* __restrict__ out)
{
    extern __shared__ unsigned smu[];
    const unsigned sbase = (unsigned)__cvta_generic_to_shared(smu);

    const int tid  = threadIdx.x;
    const int lane = tid & 31;
    const int warp = tid >> 5;
    const int g    = lane >> 2;
    const int t4   = lane & 3;

    const int b  = blockIdx.x >> 6;
    const int m0 = (blockIdx.x & 63) * TM;

    const float* xvg = g_xv + ((size_t)b * kN + m0) * kR;

    // load xv tile (128 x 32 f32 = 1024 x 16B units): row = idx>>3, u = idx&7
    #pragma unroll
    for (int i = 0; i < 4; i++) {
        const int idx = tid + 256 * i;
        const int row = idx >> 3, u = idx & 7;
        cp16(sbase + (unsigned)(row * XW + 4 * u) * 4u,
             xvg + (size_t)row * kR + 4 * u);
    }
    asm volatile("cp.async.commit_group;" ::: "memory");

    // W fragments: warp owns o-cols [warp*64, warp*64+64)
    const int oc0 = warp * 64;
    unsigned wf[8][4][2];
    #pragma unroll
    for (int ob = 0; ob < 8; ob++) {
        const float* wr = W + (size_t)(oc0 + ob * 8 + g) * kR;
        #pragma unroll
        for (int ks = 0; ks < 4; ks++) {
            wf[ob][ks][0] = f2tf(wr[ks * 8 + t4]);
            wf[ob][ks][1] = f2tf(wr[ks * 8 + t4 + 4]);
        }
    }

    asm volatile("cp.async.wait_group 0;" ::: "memory");
    __syncthreads();

    const float* c1 = (const float*)smu;
    float* stg = (float*)smu + STG_OFF + warp * STG_PER_WARP;
    float* ob_ = out + ((size_t)b * kN + m0) * kDO;

    #pragma unroll 1
    for (int mb = 0; mb < TM / 16; mb++) {
        const int r0 = mb * 16 + g;
        unsigned a[4][4];
        #pragma unroll
        for (int ks = 0; ks < 4; ks++) {
            a[ks][0] = f2tf(c1[r0       * XW + ks * 8 + t4]);
            a[ks][1] = f2tf(c1[(r0 + 8) * XW + ks * 8 + t4]);
            a[ks][2] = f2tf(c1[r0       * XW + ks * 8 + t4 + 4]);
            a[ks][3] = f2tf(c1[(r0 + 8) * XW + ks * 8 + t4 + 4]);
        }
        // compute + stage (STS.64, conflict-free under XOR-8 swizzle)
        const int sw = (g & 3) << 3;
        #pragma unroll
        for (int ob = 0; ob < 8; ob++) {
            float d0 = 0.f, d1 = 0.f, d2 = 0.f, d3 = 0.f;
            #pragma unroll
            for (int ks = 0; ks < 4; ks++)
                mma_tf32(d0, d1, d2, d3,
                         a[ks][0], a[ks][1], a[ks][2], a[ks][3],
                         wf[ob][ks][0], wf[ob][ks][1]);
            const int lc = (ob * 8 + 2 * t4) ^ sw;
            *reinterpret_cast<float2*>(&stg[g * 64 + lc]) =
                make_float2(fmaxf(d0, 0.f), fmaxf(d1, 0.f));
            *reinterpret_cast<float2*>(&stg[(g + 8) * 64 + lc]) =
                make_float2(fmaxf(d2, 0.f), fmaxf(d3, 0.f));
        }
        __syncwarp();
        // readback (LDS.128) + full-line STG.128
        const int half = lane >> 4;
        const int colw = (lane & 15) * 4;
        #pragma unroll
        for (int i = 0; i < 8; i++) {
            const int row = 2 * i + half;
            const int sc  = colw ^ ((row & 3) << 3);
            float4 val = *reinterpret_cast<float4*>(&stg[row * 64 + sc]);
            *reinterpret_cast<float4*>(
                &ob_[(size_t)(mb * 16 + row) * kDO + oc0 + colw]) = val;
        }
        __syncwarp();
    }
}

} // namespace

extern "C" void kernel_launch(void* const* d_in, const int* in_sizes, int n_in,
                              void* d_out, int out_size) {
    (void)in_sizes; (void)n_in; (void)out_size;
    const float* x = (const float*)d_in[0];
    const float* v = (const float*)d_in[1];
    const float* W = (const float*)d_in[2];
    float* out = (float*)d_out;

    prep_kernel<<<1024, 256>>>(v);

    cudaFuncSetAttribute(gemm1_kernel,
                         cudaFuncAttributeMaxDynamicSharedMemorySize, SMEM_A);
    gemm1_kernel<<<kB * (kN / TM), THREADS, SMEM_A>>>(x);

    cudaFuncSetAttribute(gemm2_kernel,
                         cudaFuncAttributeMaxDynamicSharedMemorySize, SMEM_B);
    gemm2_kernel<<<kB * (kN / TM), THREADS, SMEM_B>>>(W, out);
}

// round 12
// speedup vs baseline: 1.0681x; 1.0681x over previous
#include <cuda_runtime.h>
#include <cstdint>
#include <cstddef>

// LowRankINRLayer: out = relu( (x @ v^T) @ W^T )
//   x [16,8192,512] f32, v [16,32,512] f32, W [512,32] f32 -> out f32
//
// Round 12: R7 base (tf32 mma.sync, 4-stage cp.async KC=32, TM=128, 256 thr,
// 92KB smem, 2 CTAs/SM, prep-blocked tf32 v, W register-resident, staged
// STG.128 epilogue) with all smem fragment loads converted from scalar LDS to
// ldmatrix.m8n8.x4.b16 (1 instr / 16x8-b32 fragment): mainloop 48 LDS -> 12
// LDSM per warp-chunk, b-side cvt stays eliminated, epilogue a-frags likewise.

namespace {

constexpr int kB  = 16;
constexpr int kN  = 8192;
constexpr int kDI = 512;
constexpr int kDO = 512;
constexpr int kR  = 32;

constexpr int TM      = 128;          // rows per CTA
constexpr int KC      = 32;           // K per pipeline chunk
constexpr int NCH     = kDI / KC;     // 16
constexpr int STAGES  = 4;
constexpr int THREADS = 256;          // 8 warps

constexpr int XW = KC + 4;                          // 36 words row stride (144 B)
constexpr int XBUF = TM * XW;                       // 4608 words / stage
constexpr int VBUF = kR * XW;                       // 1152 words / stage
constexpr int V_OFF = STAGES * XBUF;                // 18432
constexpr int SMEM_WORDS = V_OFF + STAGES * VBUF;   // 23040
constexpr int SMEM_BYTES = SMEM_WORDS * 4;          // 92160 B -> 2 CTAs/SM

// epilogue staging: warp-private 16 rows x 64 words, inside stage-1..3 region
constexpr int STG_OFF = XBUF;                       // word 4608 (stage 1 start)
constexpr int STG_PER_WARP = 16 * 64;               // 1024 words (4 KB)

// tf32(RNA) scratch, filled by prep kernel
__device__ unsigned g_v[kB * kR * kDI];   // blocked [b][ck][n][kk], kk<32

__device__ __forceinline__ unsigned f2tf(float f) {
    unsigned u;
    asm("cvt.rna.tf32.f32 %0, %1;" : "=r"(u) : "f"(f));
    return u;
}
__device__ __forceinline__ unsigned f2tf_u(unsigned raw) {
    return f2tf(__uint_as_float(raw));
}

__device__ __forceinline__ void ldsm4(unsigned& r0, unsigned& r1,
                                      unsigned& r2, unsigned& r3, unsigned a) {
    asm volatile("ldmatrix.sync.aligned.m8n8.x4.shared.b16 {%0,%1,%2,%3}, [%4];"
                 : "=r"(r0), "=r"(r1), "=r"(r2), "=r"(r3) : "r"(a));
}

__device__ __forceinline__ void mma_tf32(float& d0, float& d1, float& d2, float& d3,
                                         unsigned a0, unsigned a1, unsigned a2, unsigned a3,
                                         unsigned b0, unsigned b1) {
    asm volatile(
        "mma.sync.aligned.m16n8k8.row.col.f32.tf32.tf32.f32 "
        "{%0,%1,%2,%3}, {%4,%5,%6,%7}, {%8,%9}, {%0,%1,%2,%3};"
        : "+f"(d0), "+f"(d1), "+f"(d2), "+f"(d3)
        : "r"(a0), "r"(a1), "r"(a2), "r"(a3), "r"(b0), "r"(b1));
}

__device__ __forceinline__ void cp16(unsigned dst_smem, const void* src) {
    asm volatile("cp.async.cg.shared.global [%0], [%1], 16;"
                 :: "r"(dst_smem), "l"(src) : "memory");
}

// ---- prep: v -> tf32 RNA blocked [b][ck][n][kk] (262144 elements) ----
__global__ void prep_kernel(const float* __restrict__ v) {
    int idx = blockIdx.x * 256 + threadIdx.x;   // grid 1024
    int b = idx >> 14, rem = idx & 16383;
    int n = rem >> 9, k = rem & 511;
    int ck = k >> 5, kk = k & 31;
    g_v[(b << 14) + (ck << 10) + (n << 5) + kk] = f2tf(v[idx]);
}

__global__ void __launch_bounds__(THREADS, 2)
lowrank_kernel(const float* __restrict__ x,
               const float* __restrict__ W,
               float* __restrict__ out)
{
    extern __shared__ unsigned smu[];
    const unsigned sbase = (unsigned)__cvta_generic_to_shared(smu);

    const int tid  = threadIdx.x;
    const int lane = tid & 31;
    const int warp = tid >> 5;
    const int g    = lane >> 2;
    const int t4   = lane & 3;
    const int mw   = warp * 16;

    const int b  = blockIdx.x >> 6;          // 64 tiles per batch
    const int m0 = (blockIdx.x & 63) * TM;

    const float*    xg  = x + ((size_t)b * kN + m0) * kDI;
    const unsigned* gvb = g_v + (size_t)b * (kR * kDI);

    const int vr = tid >> 3, vu = tid & 7;   // v: 256 x 16B units, 1/thread

    auto issue = [&](int c) {
        const int s = c & (STAGES - 1);
        const unsigned xd = sbase + (unsigned)(s * XBUF) * 4u;
        #pragma unroll
        for (int i = 0; i < 4; i++) {
            const int q = tid + 256 * i;     // 1024 x 16B units
            const int r = q >> 3, u = q & 7;
            cp16(xd + (unsigned)(r * XW + u * 4) * 4u,
                 xg + (size_t)r * kDI + c * KC + u * 4);
        }
        const unsigned vd = sbase + (unsigned)(V_OFF + s * VBUF) * 4u;
        cp16(vd + (unsigned)(vr * XW + vu * 4) * 4u,
             gvb + c * (kR * KC) + vr * KC + vu * 4);
        asm volatile("cp.async.commit_group;" ::: "memory");
    };

    issue(0); issue(1); issue(2);

    // ldmatrix per-lane address components (byte offsets within a stage)
    //   a-frag m16k8: lanes 0-15 -> rows mw+0..15 (+0B), lanes 16-31 -> same rows +16B
    const unsigned a_row  = (unsigned)(mw + (lane & 15));
    const unsigned a_boff = a_row * 144u + (unsigned)((lane >> 4) * 16);
    //   b-frag k8n8 pair: grp0/1 rows nbp*16+(lane&7) at +0/+16B, grp2/3 rows +8
    const unsigned b_row  = (unsigned)(((lane >> 4) << 3) + (lane & 7));
    const unsigned b_boff = b_row * 144u + (unsigned)(((lane >> 3) & 1) * 16);

    // ---- GEMM1 mainloop: acc = x_tile @ v^T (per warp: m=16, n=32) ----
    float acc[4][4] = {};

    for (int c = 0; c < NCH; ++c) {
        if (c < NCH - 2)        asm volatile("cp.async.wait_group 2;" ::: "memory");
        else if (c == NCH - 2)  asm volatile("cp.async.wait_group 1;" ::: "memory");
        else                    asm volatile("cp.async.wait_group 0;" ::: "memory");
        __syncthreads();   // chunk c ready; chunk c-1 consumed by all warps

        if (c + 3 < NCH) issue(c + 3);   // writes stage (c-1)&3, now free

        const unsigned xa = sbase + (unsigned)((c & 3) * XBUF) * 4u + a_boff;
        const unsigned vb = sbase + (unsigned)((V_OFF + (c & 3) * VBUF)) * 4u + b_boff;

        #pragma unroll
        for (int ks = 0; ks < 4; ks++) {
            unsigned ra0, ra1, ra2, ra3;
            ldsm4(ra0, ra1, ra2, ra3, xa + 32u * ks);
            unsigned a0 = f2tf_u(ra0), a1 = f2tf_u(ra1);
            unsigned a2 = f2tf_u(ra2), a3 = f2tf_u(ra3);
            #pragma unroll
            for (int nbp = 0; nbp < 2; nbp++) {
                unsigned b00, b01, b10, b11;   // (b0,b1) for nb=2nbp, 2nbp+1
                ldsm4(b00, b01, b10, b11, vb + (unsigned)(nbp * 2304) + 32u * ks);
                mma_tf32(acc[2*nbp][0],   acc[2*nbp][1],   acc[2*nbp][2],   acc[2*nbp][3],
                         a0, a1, a2, a3, b00, b01);
                mma_tf32(acc[2*nbp+1][0], acc[2*nbp+1][1], acc[2*nbp+1][2], acc[2*nbp+1][3],
                         a0, a1, a2, a3, b10, b11);
            }
        }
    }

    // ---- C1 (128x32 f32) -> smem (stage-0 region), stride 36 words ----
    __syncthreads();
    float* c1 = (float*)smu;
    #pragma unroll
    for (int nb = 0; nb < 4; nb++) {
        *reinterpret_cast<float2*>(&c1[(mw + g)     * XW + nb * 8 + 2 * t4]) =
            make_float2(acc[nb][0], acc[nb][1]);
        *reinterpret_cast<float2*>(&c1[(mw + g + 8) * XW + nb * 8 + 2 * t4]) =
            make_float2(acc[nb][2], acc[nb][3]);
    }
    __syncthreads();

    // ---- GEMM2: relu(C1 @ W^T); warp owns o-cols [warp*64, warp*64+64) ----
    const int oc0 = warp * 64;
    unsigned wf[8][4][2];
    #pragma unroll
    for (int ob = 0; ob < 8; ob++) {
        const float* wr = W + (size_t)(oc0 + ob * 8 + g) * kR;
        #pragma unroll
        for (int ks = 0; ks < 4; ks++) {
            wf[ob][ks][0] = f2tf(wr[ks * 8 + t4]);
            wf[ob][ks][1] = f2tf(wr[ks * 8 + t4 + 4]);
        }
    }

    // warp-private staging buffer: 16 rows x 64 words, XOR-8 swizzled
    float* stg = (float*)smu + STG_OFF + warp * STG_PER_WARP;
    float* ob_ = out + ((size_t)b * kN + m0) * kDO;

    #pragma unroll 1
    for (int mb = 0; mb < TM / 16; mb++) {
        // a-frags from C1 via ldmatrix (rows mb*16 + lane%16, stride 144B)
        const unsigned ca = sbase + (unsigned)(mb * 16 + (lane & 15)) * 144u
                                  + (unsigned)((lane >> 4) * 16);
        unsigned a[4][4];
        #pragma unroll
        for (int ks = 0; ks < 4; ks++) {
            unsigned r0, r1, r2, r3;
            ldsm4(r0, r1, r2, r3, ca + 32u * ks);
            a[ks][0] = f2tf_u(r0); a[ks][1] = f2tf_u(r1);
            a[ks][2] = f2tf_u(r2); a[ks][3] = f2tf_u(r3);
        }
        // compute + stage (STS.64, conflict-free under XOR-8 swizzle)
        const int sw = (g & 3) << 3;                 // same for row g and g+8
        #pragma unroll
        for (int ob = 0; ob < 8; ob++) {
            float d0 = 0.f, d1 = 0.f, d2 = 0.f, d3 = 0.f;
            #pragma unroll
            for (int ks = 0; ks < 4; ks++)
                mma_tf32(d0, d1, d2, d3,
                         a[ks][0], a[ks][1], a[ks][2], a[ks][3],
                         wf[ob][ks][0], wf[ob][ks][1]);
            const int lc = (ob * 8 + 2 * t4) ^ sw;   // XOR keeps 2-word alignment
            *reinterpret_cast<float2*>(&stg[g * 64 + lc]) =
                make_float2(fmaxf(d0, 0.f), fmaxf(d1, 0.f));
            *reinterpret_cast<float2*>(&stg[(g + 8) * 64 + lc]) =
                make_float2(fmaxf(d2, 0.f), fmaxf(d3, 0.f));
        }
        __syncwarp();
        // readback (LDS.128, conflict-free) + full-line STG.128
        const int half = lane >> 4;                  // 0/1
        const int colw = (lane & 15) * 4;            // 0..60
        #pragma unroll
        for (int i = 0; i < 8; i++) {
            const int row = 2 * i + half;
            const int sc  = colw ^ ((row & 3) << 3);
            float4 val = *reinterpret_cast<float4*>(&stg[row * 64 + sc]);
            *reinterpret_cast<float4*>(
                &ob_[(size_t)(mb * 16 + row) * kDO + oc0 + colw]) = val;
        }
        __syncwarp();   // staging reused next mb
    }
}

} // namespace

extern "C" void kernel_launch(void* const* d_in, const int* in_sizes, int n_in,
                              void* d_out, int out_size) {
    (void)in_sizes; (void)n_in; (void)out_size;
    const float* x = (const float*)d_in[0];
    const float* v = (const float*)d_in[1];
    const float* W = (const float*)d_in[2];
    float* out = (float*)d_out;

    prep_kernel<<<1024, 256>>>(v);

    cudaFuncSetAttribute(lowrank_kernel,
                         cudaFuncAttributeMaxDynamicSharedMemorySize, SMEM_BYTES);
    lowrank_kernel<<<kB * (kN / TM), THREADS, SMEM_BYTES>>>(x, W, out);
}